// round 15
// baseline (speedup 1.0000x reference)
#include <cuda_runtime.h>
#include <cuda_bf16.h>
#include <cuda_fp16.h>
#include <math.h>
#include <stdint.h>

#define NN 50000
#define EE 800000
#define ETOT (EE + NN)
#define NB_SCAN 196   // ceil(50000/256)
// node split for layer pipelining (block-aligned: 196*128)
#define NH0 25088
#define NH1 (NN - NH0)       // 24912
#define GB  391              // total gemm row blocks
#define GB0 196
#define GB1 195

// ---------------- scratch (no allocations allowed) ----------------
__device__ __align__(16) __half         g_xh0 [NN * 188];   // ping-pong lin outputs
__device__ __align__(16) __half         g_xh1 [NN * 188];
__device__ __align__(16) float          g_skip0[NN * 128];
__device__ __align__(16) float          g_skip1[NN * 128];
__device__ __align__(16) __nv_bfloat16  g_ahi [NN * 128];   // A image hi
__device__ __align__(16) __nv_bfloat16  g_alo [NN * 128];   // A image lo
__device__ __align__(16) __nv_bfloat16  g_wbhi[768 * 136];  // weight images (3 layers)
__device__ __align__(16) __nv_bfloat16  g_wblo[768 * 136];
__device__ float    g_asrc0[NN * 4];
__device__ float    g_adst0[NN * 4];
__device__ float    g_asrc1[NN * 4];
__device__ float    g_adst1[NN * 4];
// CSR scratch
__device__ int      g_deg   [NN];
__device__ int      g_ex    [NN];
__device__ int      g_bsum  [256];
__device__ int      g_rowptr[NN + 1];
__device__ int      g_cursor[NN];
__device__ int      g_csr   [ETOT];

// ---------------- helpers ----------------
__device__ __forceinline__ float lrelu(float e) { return fmaxf(e, 0.2f * e); }

__device__ __forceinline__ uint32_t smem_u32(const void* p) {
    uint32_t a;
    asm("{ .reg .u64 t; cvta.to.shared.u64 t, %1; cvt.u32.u64 %0, t; }"
        : "=r"(a) : "l"(p));
    return a;
}

__device__ __forceinline__ void split_bf16(float v, __nv_bfloat16& h, __nv_bfloat16& l) {
    h = __float2bfloat16_rn(v);
    l = __float2bfloat16_rn(v - __bfloat162float(h));
}

__device__ __forceinline__ uint32_t pack_bf16(__nv_bfloat16 a, __nv_bfloat16 b) {
    return (uint32_t)__bfloat16_as_ushort(a) |
           ((uint32_t)__bfloat16_as_ushort(b) << 16);
}

__device__ __forceinline__ void ldsm_x4(uint32_t& r0, uint32_t& r1,
                                        uint32_t& r2, uint32_t& r3, uint32_t addr) {
    asm volatile("ldmatrix.sync.aligned.m8n8.x4.shared.b16 {%0,%1,%2,%3}, [%4];"
                 : "=r"(r0), "=r"(r1), "=r"(r2), "=r"(r3) : "r"(addr));
}

__device__ __forceinline__ void mma_bf16(float* c, const uint32_t* a, const uint32_t* b) {
    asm volatile(
        "mma.sync.aligned.m16n8k16.row.col.f32.bf16.bf16.f32 "
        "{%0,%1,%2,%3}, {%4,%5,%6,%7}, {%8,%9}, {%0,%1,%2,%3};"
        : "+f"(c[0]), "+f"(c[1]), "+f"(c[2]), "+f"(c[3])
        : "r"(a[0]), "r"(a[1]), "r"(a[2]), "r"(a[3]), "r"(b[0]), "r"(b[1]));
}

// SMEM layout (bytes), stride 136 bf16 = 272B per row
#define AST       136
#define BST       136
#define SM_AHI    0
#define SM_ALO    (128 * AST * 2)                 // 34816
#define SM_BHI    (SM_ALO + 128 * AST * 2)        // 69632
#define SM_BLO    (SM_BHI + 256 * BST * 2)        // 139264
#define SM_TOTAL  (SM_BLO + 256 * BST * 2)        // 208896

// ================= merged conversion kernel =================
__global__ void conv_all(
    const float* __restrict__ w0l, const float* __restrict__ w0s,
    const float* __restrict__ w1l, const float* __restrict__ w1s,
    const float* __restrict__ w2l, const float* __restrict__ w2s,
    const float* __restrict__ X,
    __nv_bfloat16* __restrict__ whi, __nv_bfloat16* __restrict__ wlo,
    __nv_bfloat16* __restrict__ ahi, __nv_bfloat16* __restrict__ alo)
{
    int bx = blockIdx.x;
    if (bx < 384) {
        int idx = bx * 256 + threadIdx.x;          // over 768*128
        int n = idx >> 7, k = idx & 127;
        int layer = n >> 8, nl = n & 255;
        float v = 0.f;
        if (layer == 0) {
            v = (nl < 128) ? w0l[k * 128 + nl] : w0s[k * 128 + (nl - 128)];
        } else if (layer == 1) {
            v = (nl < 128) ? w1l[k * 128 + nl] : w1s[k * 128 + (nl - 128)];
        } else {
            if (nl < 188) v = w2l[k * 188 + nl];
            else if (nl >= 192 && nl < 239) v = w2s[k * 47 + (nl - 192)];
        }
        __nv_bfloat16 h, l;
        split_bf16(v, h, l);
        whi[n * 136 + k] = h;
        wlo[n * 136 + k] = l;
    } else {
        int idx = (bx - 384) * 256 + threadIdx.x;  // over NN*32 float4s
        if (idx >= NN * 32) return;
        float4 v = *(const float4*)(X + (long long)idx * 4);
        __nv_bfloat16 h0, l0, h1, l1, h2, l2, h3, l3;
        split_bf16(v.x, h0, l0); split_bf16(v.y, h1, l1);
        split_bf16(v.z, h2, l2); split_bf16(v.w, h3, l3);
        uint2 ph, pl;
        ph.x = pack_bf16(h0, h1); ph.y = pack_bf16(h2, h3);
        pl.x = pack_bf16(l0, l1); pl.y = pack_bf16(l2, l3);
        *(uint2*)((char*)ahi + (long long)idx * 8) = ph;
        *(uint2*)((char*)alo + (long long)idx * 8) = pl;
    }
}

// ================= CSR build =================
__global__ void k_count(const int* __restrict__ ei, int* __restrict__ deg) {
    int i = blockIdx.x * blockDim.x + threadIdx.x;
    if (i >= ETOT) return;
    int d = (i < EE) ? ei[EE + i] : i - EE;
    atomicAdd(&deg[d], 1);
}
__global__ void k_scan1(const int* __restrict__ deg, int* __restrict__ ex,
                        int* __restrict__ bsum) {
    __shared__ int sh[256];
    int t = threadIdx.x;
    int i = blockIdx.x * 256 + t;
    int v = (i < NN) ? deg[i] : 0;
    sh[t] = v;
    __syncthreads();
    for (int off = 1; off < 256; off <<= 1) {
        int a = (t >= off) ? sh[t - off] : 0;
        __syncthreads();
        sh[t] += a;
        __syncthreads();
    }
    if (i < NN) ex[i] = sh[t] - v;
    if (t == 255) bsum[blockIdx.x] = sh[255];
}
__global__ void k_scan23(const int* __restrict__ ex, const int* __restrict__ bsum,
                         int* __restrict__ rowptr, int* __restrict__ cursor) {
    __shared__ int sh[256];
    int t = threadIdx.x, b = blockIdx.x;
    sh[t] = (t < b) ? bsum[t] : 0;     // b <= 195 < 256
    __syncthreads();
    for (int off = 128; off; off >>= 1) {
        if (t < off) sh[t] += sh[t + off];
        __syncthreads();
    }
    int bpre = sh[0];
    int i = b * 256 + t;
    if (i < NN) {
        int r = ex[i] + bpre;
        rowptr[i] = r;
        cursor[i] = r;
    }
    if (i == 0) rowptr[NN] = ETOT;
}
__global__ void k_fill(const int* __restrict__ ei, int* __restrict__ cursor,
                       int* __restrict__ csr) {
    int i = blockIdx.x * blockDim.x + threadIdx.x;
    if (i >= ETOT) return;
    int s, d;
    if (i < EE) { s = ei[i]; d = ei[EE + i]; } else { s = d = i - EE; }
    int pos = atomicAdd(&cursor[d], 1);
    csr[pos] = s;
}

// ============ staging (pure copies) + mma mainloop ============
__device__ __forceinline__ void stage_A2(char* sm, const __nv_bfloat16* __restrict__ ahi,
                                         const __nv_bfloat16* __restrict__ alo,
                                         int row0, int tid) {
    #pragma unroll
    for (int jj = 0; jj < 4; jj++) {
        int i = tid + jj * 512;          // 0..2047
        int r = i >> 4, q = i & 15;      // row, uint4 idx (16B)
        uint4 vh = make_uint4(0, 0, 0, 0), vl = make_uint4(0, 0, 0, 0);
        if (row0 + r < NN) {
            long long bofs = ((long long)(row0 + r) * 128 + q * 8) * 2;
            vh = *(const uint4*)((const char*)ahi + bofs);
            vl = *(const uint4*)((const char*)alo + bofs);
        }
        *(uint4*)(sm + SM_AHI + r * (AST * 2) + q * 16) = vh;
        *(uint4*)(sm + SM_ALO + r * (AST * 2) + q * 16) = vl;
    }
}

__device__ __forceinline__ void stage_B2(char* sm, const __nv_bfloat16* __restrict__ whi,
                                         const __nv_bfloat16* __restrict__ wlo, int tid) {
    #pragma unroll
    for (int jj = 0; jj < 9; jj++) {
        int i = tid + jj * 512;
        if (i < 4352) {
            *(uint4*)(sm + SM_BHI + i * 16) = *(const uint4*)((const char*)whi + i * 16);
            *(uint4*)(sm + SM_BLO + i * 16) = *(const uint4*)((const char*)wlo + i * 16);
        }
    }
}

__device__ __forceinline__ void mma_mainloop(char* sm, float acc[2][8][4],
                                             int wid, int lane) {
    const uint32_t sb = smem_u32(sm);
    const int wm = wid >> 2, wn = wid & 3;
    const int m0r = wm * 32, n0 = wn * 64;
    const int ar = (lane & 15), ak = (lane >> 4) * 8;
    const int bn = ((lane >> 4) * 8) + (lane & 7);
    const int bk = ((lane >> 3) & 1) * 8;

    #pragma unroll
    for (int ks = 0; ks < 8; ks++) {
        int k0 = ks * 16;
        uint32_t ahi[2][4], alo[2][4], bhi[8][2], blo[8][2];
        #pragma unroll
        for (int mt = 0; mt < 2; mt++) {
            uint32_t addr = sb + SM_AHI + (m0r + mt * 16 + ar) * (AST * 2) + (k0 + ak) * 2;
            ldsm_x4(ahi[mt][0], ahi[mt][1], ahi[mt][2], ahi[mt][3], addr);
        }
        #pragma unroll
        for (int p = 0; p < 4; p++) {
            uint32_t addr = sb + SM_BHI + (n0 + p * 16 + bn) * (BST * 2) + (k0 + bk) * 2;
            ldsm_x4(bhi[2 * p][0], bhi[2 * p][1], bhi[2 * p + 1][0], bhi[2 * p + 1][1], addr);
        }
        #pragma unroll
        for (int mt = 0; mt < 2; mt++)
            #pragma unroll
            for (int nt = 0; nt < 8; nt++)
                mma_bf16(acc[mt][nt], ahi[mt], bhi[nt]);
        #pragma unroll
        for (int p = 0; p < 4; p++) {
            uint32_t addr = sb + SM_BLO + (n0 + p * 16 + bn) * (BST * 2) + (k0 + bk) * 2;
            ldsm_x4(blo[2 * p][0], blo[2 * p][1], blo[2 * p + 1][0], blo[2 * p + 1][1], addr);
        }
        #pragma unroll
        for (int mt = 0; mt < 2; mt++)
            #pragma unroll
            for (int nt = 0; nt < 8; nt++)
                mma_bf16(acc[mt][nt], ahi[mt], blo[nt]);
        #pragma unroll
        for (int mt = 0; mt < 2; mt++) {
            uint32_t addr = sb + SM_ALO + (m0r + mt * 16 + ar) * (AST * 2) + (k0 + ak) * 2;
            ldsm_x4(alo[mt][0], alo[mt][1], alo[mt][2], alo[mt][3], addr);
        }
        #pragma unroll
        for (int mt = 0; mt < 2; mt++)
            #pragma unroll
            for (int nt = 0; nt < 8; nt++)
                mma_bf16(acc[mt][nt], alo[mt], bhi[nt]);
    }
}

// ================= dual GEMM, layers 0/1 + fused attention scores =========
__global__ __launch_bounds__(512, 1) void gemm_dual_128(
    const __nv_bfloat16* __restrict__ ahi, const __nv_bfloat16* __restrict__ alo,
    const __nv_bfloat16* __restrict__ whi, const __nv_bfloat16* __restrict__ wlo,
    const float* __restrict__ AttS, const float* __restrict__ AttD,
    __half* __restrict__ Xh, float* __restrict__ Oskip,
    float* __restrict__ asrc, float* __restrict__ adst, int bb)
{
    extern __shared__ char sm[];
    const int tid = threadIdx.x;
    const int wid = tid >> 5, lane = tid & 31;
    const int row0 = (blockIdx.x + bb) << 7;

    stage_A2(sm, ahi, alo, row0, tid);
    stage_B2(sm, whi, wlo, tid);
    __syncthreads();

    float acc[2][8][4];
    #pragma unroll
    for (int i = 0; i < 2; i++)
        #pragma unroll
        for (int j = 0; j < 8; j++)
            #pragma unroll
            for (int q = 0; q < 4; q++) acc[i][j][q] = 0.f;

    mma_mainloop(sm, acc, wid, lane);

    const int wm = wid >> 2, wn = wid & 3;
    const int g = lane >> 2, t = lane & 3;

    #pragma unroll
    for (int mt = 0; mt < 2; mt++) {
        #pragma unroll
        for (int half_ = 0; half_ < 2; half_++) {
            int row = row0 + wm * 32 + mt * 16 + g + half_ * 8;
            if (row >= NN) continue;
            #pragma unroll
            for (int nt = 0; nt < 8; nt++) {
                int c = wn * 64 + nt * 8 + t * 2;
                float2 v = make_float2(acc[mt][nt][half_ * 2 + 0],
                                       acc[mt][nt][half_ * 2 + 1]);
                if (c < 128)
                    *(__half2*)(Xh + (long long)row * 128 + c) = __float22half2_rn(v);
                else
                    *(float2*)(Oskip + (long long)row * 128 + (c - 128)) = v;
            }
        }
    }

    if (wn < 2) {
        #pragma unroll
        for (int mt = 0; mt < 2; mt++) {
            #pragma unroll
            for (int half_ = 0; half_ < 2; half_++) {
                float ps0 = 0.f, ps1 = 0.f, pd0 = 0.f, pd1 = 0.f;
                #pragma unroll
                for (int nt = 0; nt < 8; nt++) {
                    #pragma unroll
                    for (int q = 0; q < 2; q++) {
                        int c = wn * 64 + nt * 8 + t * 2 + q;
                        float v = acc[mt][nt][half_ * 2 + q];
                        float cs = AttS[c], cd = AttD[c];
                        if (nt < 4) { ps0 += v * cs; pd0 += v * cd; }
                        else        { ps1 += v * cs; pd1 += v * cd; }
                    }
                }
                ps0 += __shfl_xor_sync(0xFFFFFFFFu, ps0, 1);
                ps0 += __shfl_xor_sync(0xFFFFFFFFu, ps0, 2);
                ps1 += __shfl_xor_sync(0xFFFFFFFFu, ps1, 1);
                ps1 += __shfl_xor_sync(0xFFFFFFFFu, ps1, 2);
                pd0 += __shfl_xor_sync(0xFFFFFFFFu, pd0, 1);
                pd0 += __shfl_xor_sync(0xFFFFFFFFu, pd0, 2);
                pd1 += __shfl_xor_sync(0xFFFFFFFFu, pd1, 1);
                pd1 += __shfl_xor_sync(0xFFFFFFFFu, pd1, 2);
                int row = row0 + wm * 32 + mt * 16 + g + half_ * 8;
                if (t == 0 && row < NN) {
                    int h0 = wn * 2, h1 = wn * 2 + 1;
                    asrc[row * 4 + h0] = ps0;
                    asrc[row * 4 + h1] = ps1;
                    adst[row * 4 + h0] = pd0;
                    adst[row * 4 + h1] = pd1;
                }
            }
        }
    }
}

// ================= layer-2 GEMM + fused attention scores ==================
__global__ __launch_bounds__(512, 1) void gemm_l2(
    const __nv_bfloat16* __restrict__ ahi, const __nv_bfloat16* __restrict__ alo,
    const __nv_bfloat16* __restrict__ whi, const __nv_bfloat16* __restrict__ wlo,
    const float* __restrict__ AttS, const float* __restrict__ AttD,
    __half* __restrict__ Xh, float* __restrict__ Oskip,
    float* __restrict__ asrc, float* __restrict__ adst, int bb)
{
    extern __shared__ char sm[];
    const int tid = threadIdx.x;
    const int wid = tid >> 5, lane = tid & 31;
    const int row0 = (blockIdx.x + bb) << 7;

    stage_A2(sm, ahi, alo, row0, tid);
    stage_B2(sm, whi, wlo, tid);
    __syncthreads();

    float acc[2][8][4];
    #pragma unroll
    for (int i = 0; i < 2; i++)
        #pragma unroll
        for (int j = 0; j < 8; j++)
            #pragma unroll
            for (int q = 0; q < 4; q++) acc[i][j][q] = 0.f;

    mma_mainloop(sm, acc, wid, lane);

    const int wm = wid >> 2, wn = wid & 3;
    const int g = lane >> 2, t = lane & 3;
    #pragma unroll
    for (int mt = 0; mt < 2; mt++) {
        #pragma unroll
        for (int half_ = 0; half_ < 2; half_++) {
            int row = row0 + wm * 32 + mt * 16 + g + half_ * 8;
            if (row >= NN) continue;
            #pragma unroll
            for (int nt = 0; nt < 8; nt++) {
                int c = wn * 64 + nt * 8 + t * 2;
                float2 v = make_float2(acc[mt][nt][half_ * 2 + 0],
                                       acc[mt][nt][half_ * 2 + 1]);
                if (c < 188) {
                    *(__half2*)(Xh + (long long)row * 188 + c) = __float22half2_rn(v);
                } else {
                    #pragma unroll
                    for (int q = 0; q < 2; q++) {
                        int cc = c + q;
                        if (cc >= 192 && cc < 239)
                            Oskip[(long long)row * 47 + (cc - 192)] = (q ? v.y : v.x);
                    }
                }
            }
        }
    }

    // ---- fused layer-2 attention scores (head = c/47) ----
    __syncthreads();
    float* satt = (float*)sm;
    for (int i = tid; i < 128 * 8; i += 512) satt[i] = 0.f;
    __syncthreads();

    #pragma unroll
    for (int mt = 0; mt < 2; mt++) {
        #pragma unroll
        for (int half_ = 0; half_ < 2; half_++) {
            float ps[4] = {0.f, 0.f, 0.f, 0.f}, pd[4] = {0.f, 0.f, 0.f, 0.f};
            #pragma unroll
            for (int nt = 0; nt < 8; nt++) {
                #pragma unroll
                for (int q = 0; q < 2; q++) {
                    int c = wn * 64 + nt * 8 + t * 2 + q;
                    if (c < 188) {
                        float v = acc[mt][nt][half_ * 2 + q];
                        int h = c / 47;
                        ps[h] += v * AttS[c];
                        pd[h] += v * AttD[c];
                    }
                }
            }
            #pragma unroll
            for (int h = 0; h < 4; h++) {
                ps[h] += __shfl_xor_sync(0xFFFFFFFFu, ps[h], 1);
                ps[h] += __shfl_xor_sync(0xFFFFFFFFu, ps[h], 2);
                pd[h] += __shfl_xor_sync(0xFFFFFFFFu, pd[h], 1);
                pd[h] += __shfl_xor_sync(0xFFFFFFFFu, pd[h], 2);
            }
            if (t == 0) {
                int rloc = wm * 32 + mt * 16 + g + half_ * 8;
                #pragma unroll
                for (int h = 0; h < 4; h++) {
                    atomicAdd(&satt[rloc * 8 + h * 2 + 0], ps[h]);
                    atomicAdd(&satt[rloc * 8 + h * 2 + 1], pd[h]);
                }
            }
        }
    }
    __syncthreads();
    for (int i = tid; i < 128 * 4; i += 512) {
        int rloc = i >> 2, h = i & 3;
        int row = row0 + rloc;
        if (row < NN) {
            asrc[row * 4 + h] = satt[rloc * 8 + h * 2 + 0];
            adst[row * 4 + h] = satt[rloc * 8 + h * 2 + 1];
        }
    }
}

// ================= fused GAT aggregation (F=128), single-pass =============
__global__ __launch_bounds__(256) void gat_agg_128(
    const int* __restrict__ rowptr, const int* __restrict__ csr,
    const float* __restrict__ asrc, const float* __restrict__ adst,
    const __half* __restrict__ xh, const float* __restrict__ skipb,
    const float* __restrict__ bias, const float* __restrict__ skip_b,
    __nv_bfloat16* __restrict__ ahi, __nv_bfloat16* __restrict__ alo,
    int wbase, int wcount)
{
    int wi = (blockIdx.x * blockDim.x + threadIdx.x) >> 5;
    if (wi >= wcount) return;
    int w = wbase + wi;
    int lane = threadIdx.x & 31;
    int h = lane >> 3;
    int beg = rowptr[w], end = rowptr[w + 1];
    float adh = adst[4 * w + h];

    float sh = 0.f;
    float4 acc = make_float4(0.f, 0.f, 0.f, 0.f);
    #pragma unroll 4
    for (int e = beg; e < end; e++) {
        int s = csr[e];
        float as = asrc[4 * s + h];
        float wl = __expf(lrelu(as + adh));
        sh += wl;
        uint2 raw = *(const uint2*)(xh + (long long)s * 128 + lane * 4);
        float2 p0 = __half22float2(*(const __half2*)&raw.x);
        float2 p1 = __half22float2(*(const __half2*)&raw.y);
        acc.x += wl * p0.x; acc.y += wl * p0.y;
        acc.z += wl * p1.x; acc.w += wl * p1.y;
    }
    float inv = 1.f / (sh + 1e-16f);

    int base = w * 128 + lane * 4;
    float4 sk = *(const float4*)(skipb + base);
    float4 bi = *(const float4*)(bias + lane * 4);
    float4 sb = *(const float4*)(skip_b + lane * 4);
    float4 o;
    o.x = acc.x * inv + sk.x + bi.x + sb.x;
    o.y = acc.y * inv + sk.y + bi.y + sb.y;
    o.z = acc.z * inv + sk.z + bi.z + sb.z;
    o.w = acc.w * inv + sk.w + bi.w + sb.w;
    o.x = o.x > 0.f ? o.x : expm1f(o.x);
    o.y = o.y > 0.f ? o.y : expm1f(o.y);
    o.z = o.z > 0.f ? o.z : expm1f(o.z);
    o.w = o.w > 0.f ? o.w : expm1f(o.w);

    __nv_bfloat16 h0, l0, h1, l1, h2, l2, h3, l3;
    split_bf16(o.x, h0, l0); split_bf16(o.y, h1, l1);
    split_bf16(o.z, h2, l2); split_bf16(o.w, h3, l3);
    uint2 ph, pl;
    ph.x = pack_bf16(h0, h1); ph.y = pack_bf16(h2, h3);
    pl.x = pack_bf16(l0, l1); pl.y = pack_bf16(l2, l3);
    *(uint2*)((char*)ahi + (long long)base * 2) = ph;
    *(uint2*)((char*)alo + (long long)base * 2) = pl;
}

// ================= fused GAT aggregation (layer 2, head-mean) =============
__global__ __launch_bounds__(256) void gat_agg_188(
    const int* __restrict__ rowptr, const int* __restrict__ csr,
    const float* __restrict__ asrc, const float* __restrict__ adst,
    const __half* __restrict__ xh, const float* __restrict__ skipb,
    const float* __restrict__ bias2, const float* __restrict__ skip_b2,
    float* __restrict__ out)
{
    int w = (blockIdx.x * blockDim.x + threadIdx.x) >> 5;
    if (w >= NN) return;
    int lane = threadIdx.x & 31;
    int beg = rowptr[w], end = rowptr[w + 1];
    float4 ad = *(const float4*)(adst + 4 * w);

    float4 s4 = make_float4(0.f, 0.f, 0.f, 0.f);
    float a00 = 0.f, a01 = 0.f, a02 = 0.f, a03 = 0.f;
    float a10 = 0.f, a11 = 0.f, a12 = 0.f, a13 = 0.f;
    int o1 = lane + 32;
    #pragma unroll 2
    for (int e = beg; e < end; e++) {
        int s = csr[e];
        float4 a = *(const float4*)(asrc + 4 * s);
        float wx = __expf(lrelu(a.x + ad.x));
        float wy = __expf(lrelu(a.y + ad.y));
        float wz = __expf(lrelu(a.z + ad.z));
        float ww = __expf(lrelu(a.w + ad.w));
        s4.x += wx; s4.y += wy; s4.z += wz; s4.w += ww;
        const __half* row = xh + (long long)s * 188;
        a00 += wx * __half2float(row[lane]);
        a01 += wy * __half2float(row[47 + lane]);
        a02 += wz * __half2float(row[94 + lane]);
        a03 += ww * __half2float(row[141 + lane]);
        if (o1 < 47) {
            a10 += wx * __half2float(row[o1]);
            a11 += wy * __half2float(row[47 + o1]);
            a12 += wz * __half2float(row[94 + o1]);
            a13 += ww * __half2float(row[141 + o1]);
        }
    }
    float ix = 1.f / (s4.x + 1e-16f);
    float iy = 1.f / (s4.y + 1e-16f);
    float iz = 1.f / (s4.z + 1e-16f);
    float iw = 1.f / (s4.w + 1e-16f);

    {
        int o = lane;
        float v = 0.25f * (a00 * ix + a01 * iy + a02 * iz + a03 * iw);
        out[w * 47 + o] = v + bias2[o] + skipb[w * 47 + o] + skip_b2[o];
    }
    if (o1 < 47) {
        float v = 0.25f * (a10 * ix + a11 * iy + a12 * iz + a13 * iw);
        out[w * 47 + o1] = v + bias2[o1] + skipb[w * 47 + o1] + skip_b2[o1];
    }
}

// ---------------- launch ----------------
extern "C" void kernel_launch(void* const* d_in, const int* in_sizes, int n_in,
                              void* d_out, int out_size)
{
    const float* x        = (const float*)d_in[0];
    const int*   ei       = (const int*)  d_in[1];
    const float* lin_w0   = (const float*)d_in[2];
    const float* att_src0 = (const float*)d_in[3];
    const float* att_dst0 = (const float*)d_in[4];
    const float* bias0    = (const float*)d_in[5];
    const float* skip_w0  = (const float*)d_in[6];
    const float* skip_b0  = (const float*)d_in[7];
    const float* lin_w1   = (const float*)d_in[8];
    const float* att_src1 = (const float*)d_in[9];
    const float* att_dst1 = (const float*)d_in[10];
    const float* bias1    = (const float*)d_in[11];
    const float* skip_w1  = (const float*)d_in[12];
    const float* skip_b1  = (const float*)d_in[13];
    const float* lin_w2   = (const float*)d_in[14];
    const float* att_src2 = (const float*)d_in[15];
    const float* att_dst2 = (const float*)d_in[16];
    const float* bias2    = (const float*)d_in[17];
    const float* skip_w2  = (const float*)d_in[18];
    const float* skip_b2  = (const float*)d_in[19];
    float* out = (float*)d_out;

    __half *xh0, *xh1; float *skip0, *skip1, *as0, *ad0, *as1, *ad1;
    __nv_bfloat16 *ahi, *alo, *wbhi, *wblo;
    int *deg, *ex, *bsum, *rowptr, *cursor, *csr;
    cudaGetSymbolAddress((void**)&xh0,    g_xh0);
    cudaGetSymbolAddress((void**)&xh1,    g_xh1);
    cudaGetSymbolAddress((void**)&skip0,  g_skip0);
    cudaGetSymbolAddress((void**)&skip1,  g_skip1);
    cudaGetSymbolAddress((void**)&ahi,    g_ahi);
    cudaGetSymbolAddress((void**)&alo,    g_alo);
    cudaGetSymbolAddress((void**)&wbhi,   g_wbhi);
    cudaGetSymbolAddress((void**)&wblo,   g_wblo);
    cudaGetSymbolAddress((void**)&as0,    g_asrc0);
    cudaGetSymbolAddress((void**)&ad0,    g_adst0);
    cudaGetSymbolAddress((void**)&as1,    g_asrc1);
    cudaGetSymbolAddress((void**)&ad1,    g_adst1);
    cudaGetSymbolAddress((void**)&deg,    g_deg);
    cudaGetSymbolAddress((void**)&ex,     g_ex);
    cudaGetSymbolAddress((void**)&bsum,   g_bsum);
    cudaGetSymbolAddress((void**)&rowptr, g_rowptr);
    cudaGetSymbolAddress((void**)&cursor, g_cursor);
    cudaGetSymbolAddress((void**)&csr,    g_csr);

    static cudaStream_t s1 = nullptr;
    static cudaEvent_t ev_fork = nullptr, ev_join = nullptr;
    static cudaEvent_t e1 = nullptr, e2 = nullptr, e3 = nullptr, e4 = nullptr;
    static int once = 0;
    if (!once) {
        cudaFuncSetAttribute(gemm_dual_128, cudaFuncAttributeMaxDynamicSharedMemorySize, SM_TOTAL);
        cudaFuncSetAttribute(gemm_l2,       cudaFuncAttributeMaxDynamicSharedMemorySize, SM_TOTAL);
        cudaStreamCreateWithFlags(&s1, cudaStreamNonBlocking);
        cudaEventCreateWithFlags(&ev_fork, cudaEventDisableTiming);
        cudaEventCreateWithFlags(&ev_join, cudaEventDisableTiming);
        cudaEventCreateWithFlags(&e1, cudaEventDisableTiming);
        cudaEventCreateWithFlags(&e2, cudaEventDisableTiming);
        cudaEventCreateWithFlags(&e3, cudaEventDisableTiming);
        cudaEventCreateWithFlags(&e4, cudaEventDisableTiming);
        once = 1;
    }

    const int EBLK = (ETOT + 255) / 256;             // 3321
    const int WG0 = (NH0 * 32) / 256;                // 3136
    const int WG1 = (NH1 * 32 + 255) / 256;          // 3114
    const int WGRD = (NN * 32 + 255) / 256;          // 6250

    // ---------- fork: CSR build on side stream, concurrent with conv+gemm0 --
    cudaEventRecord(ev_fork, 0);
    cudaStreamWaitEvent(s1, ev_fork, 0);
    cudaMemsetAsync(deg, 0, NN * sizeof(int), s1);
    k_count<<<EBLK, 256, 0, s1>>>(ei, deg);
    k_scan1<<<NB_SCAN, 256, 0, s1>>>(deg, ex, bsum);
    k_scan23<<<NB_SCAN, 256, 0, s1>>>(ex, bsum, rowptr, cursor);
    k_fill<<<EBLK, 256, 0, s1>>>(ei, cursor, csr);
    cudaEventRecord(ev_join, s1);

    // ---------- main stream: conversions + layer-0 GEMM (full) ----------
    conv_all<<<384 + (NN * 32 + 255) / 256, 256>>>(
        lin_w0, skip_w0, lin_w1, skip_w1, lin_w2, skip_w2, x,
        wbhi, wblo, ahi, alo);
    gemm_dual_128<<<GB, 512, SM_TOTAL>>>(ahi, alo, wbhi, wblo,
                                         att_src0, att_dst0, xh0, skip0, as0, ad0, 0);

    cudaStreamWaitEvent(0, ev_join, 0);   // aggregation needs the CSR

    // ---------- layer 0 agg (split) / layer 1 gemm (pipelined) ----------
    gat_agg_128<<<WG0, 256>>>(rowptr, csr, as0, ad0, xh0, skip0, bias0, skip_b0,
                              ahi, alo, 0, NH0);
    cudaEventRecord(e1, 0);
    gat_agg_128<<<WG1, 256>>>(rowptr, csr, as0, ad0, xh0, skip0, bias0, skip_b0,
                              ahi, alo, NH0, NH1);
    cudaStreamWaitEvent(s1, e1, 0);
    gemm_dual_128<<<GB0, 512, SM_TOTAL, s1>>>(ahi, alo, wbhi + 256 * 136, wblo + 256 * 136,
                                              att_src1, att_dst1, xh1, skip1, as1, ad1, 0);
    cudaEventRecord(e2, s1);
    gemm_dual_128<<<GB1, 512, SM_TOTAL>>>(ahi, alo, wbhi + 256 * 136, wblo + 256 * 136,
                                          att_src1, att_dst1, xh1, skip1, as1, ad1, GB0);
    cudaStreamWaitEvent(0, e2, 0);        // full gemm1 done

    // ---------- layer 1 agg (split) / layer 2 gemm (pipelined) ----------
    gat_agg_128<<<WG0, 256>>>(rowptr, csr, as1, ad1, xh1, skip1, bias1, skip_b1,
                              ahi, alo, 0, NH0);
    cudaEventRecord(e3, 0);
    gat_agg_128<<<WG1, 256>>>(rowptr, csr, as1, ad1, xh1, skip1, bias1, skip_b1,
                              ahi, alo, NH0, NH1);
    cudaStreamWaitEvent(s1, e3, 0);
    gemm_l2<<<GB0, 512, SM_TOTAL, s1>>>(ahi, alo, wbhi + 512 * 136, wblo + 512 * 136,
                                        att_src2, att_dst2, xh0, skip0, as0, ad0, 0);
    cudaEventRecord(e4, s1);
    gemm_l2<<<GB1, 512, SM_TOTAL>>>(ahi, alo, wbhi + 512 * 136, wblo + 512 * 136,
                                    att_src2, att_dst2, xh0, skip0, as0, ad0, GB0);
    cudaStreamWaitEvent(0, e4, 0);        // full gemm2 done

    // ---------- layer 2 aggregation ----------
    gat_agg_188<<<WGRD, 256>>>(rowptr, csr, as0, ad0, xh0, skip0, bias2, skip_b2, out);
}